// round 13
// baseline (speedup 1.0000x reference)
#include <cuda_runtime.h>
#include <math.h>

#define BB  2
#define NN  8192
#define MM  4096
#define CC  64
#define KK  15      // K-1 neighbors actually used
#define HH  256
#define NCHUNK 8
#define CHM (MM / NCHUNK)   // 512

// Scratch (allocation-free rule: __device__ globals)
__device__ unsigned long long g_nn_part[BB * NCHUNK * NN];
__device__ int   g_knn[BB * MM * KK];
// prepped weights
__device__ float g_l1A[HH * 4];          // [c][{A0,A1,A2,B}]  (BN-folded)
__device__ float g_l1T[HH * 4];          // [c][{A3,A4,A5,0}]  (BN-folded)
__device__ float g_wt2b[HH * CC];        // [c][o]
__device__ float g_wt1a[3 * CC * CC];    // [c][o]
__device__ float g_wt1b[CC * CC];        // [c][o]
__device__ float g_f1s[CC];              // g1a*invs
__device__ float g_f1b[CC];              // b1a*g' + bt1a

#define FMA2(acc, a, b) \
    asm("fma.rn.f32x2 %0, %1, %2, %0;" : "+l"(acc) : "l"(a), "l"(b))
#define UNPK2(lo, hi, v) \
    asm("mov.b64 {%0, %1}, %2;" : "=f"(lo), "=f"(hi) : "l"(v))
#define DUP2(out, v) \
    asm("mov.b64 %0, {%1, %1};" : "=l"(out) : "f"(v))

static __device__ __forceinline__ unsigned long long packkey(float d, int idx) {
    return ((unsigned long long)__float_as_uint(d) << 32) | (unsigned)idx;
}

// ---------------------------------------------------------------------------
// Kernel P: fold BN + transpose weight prep.
// ---------------------------------------------------------------------------
__global__ __launch_bounds__(256) void prep_kernel(
    const float* __restrict__ w2a, const float* __restrict__ b2a,
    const float* __restrict__ g2a, const float* __restrict__ bt2a,
    const float* __restrict__ w2b,
    const float* __restrict__ w1a, const float* __restrict__ b1a,
    const float* __restrict__ g1a, const float* __restrict__ bt1a,
    const float* __restrict__ w1b)
{
    const float invs = rsqrtf(1.0f + 1e-5f);
    const int t = blockIdx.x * 256 + threadIdx.x;
    const int stride = gridDim.x * 256;

    for (int c = t; c < HH; c += stride) {
        const float gp = g2a[c] * invs;
        g_l1A[c * 4 + 0] = w2a[c * 6 + 0] * gp;
        g_l1A[c * 4 + 1] = w2a[c * 6 + 1] * gp;
        g_l1A[c * 4 + 2] = w2a[c * 6 + 2] * gp;
        g_l1A[c * 4 + 3] = b2a[c] * gp + bt2a[c];
        g_l1T[c * 4 + 0] = w2a[c * 6 + 3] * gp;
        g_l1T[c * 4 + 1] = w2a[c * 6 + 4] * gp;
        g_l1T[c * 4 + 2] = w2a[c * 6 + 5] * gp;
        g_l1T[c * 4 + 3] = 0.f;
    }
    for (int idx = t; idx < HH * CC; idx += stride) {
        int c = idx / CC, o = idx - c * CC;
        g_wt2b[idx] = w2b[o * HH + c];
    }
    for (int idx = t; idx < 3 * CC * CC; idx += stride) {
        int c = idx / CC, o = idx - c * CC;
        g_wt1a[idx] = w1a[o * (3 * CC) + c];
    }
    for (int idx = t; idx < CC * CC; idx += stride) {
        int c = idx / CC, o = idx - c * CC;
        g_wt1b[idx] = w1b[o * CC + c];
    }
    for (int o = t; o < CC; o += stride) {
        const float s = g1a[o] * invs;
        g_f1s[o] = s;
        g_f1b[o] = b1a[o] * s + bt1a[o];
    }
}

// ---------------------------------------------------------------------------
// Kernel A: partial argmin over a 512-candidate chunk. float4 smem tile;
// exact difference-based distance (matches reference conditioning).
// ---------------------------------------------------------------------------
__global__ __launch_bounds__(128) void nn_part_kernel(
    const float* __restrict__ pcl, const float* __restrict__ pcl_noise)
{
    const int b = blockIdx.z;
    const int chunk = blockIdx.y;
    const int n = blockIdx.x * 128 + threadIdx.x;
    const float* pb = pcl + (size_t)b * MM * 3 + (size_t)chunk * CHM * 3;

    const float qx = pcl_noise[((size_t)b * NN + n) * 3 + 0];
    const float qy = pcl_noise[((size_t)b * NN + n) * 3 + 1];
    const float qz = pcl_noise[((size_t)b * NN + n) * 3 + 2];

    __shared__ float4 sp[CHM];
    for (int m = threadIdx.x; m < CHM; m += 128)
        sp[m] = make_float4(pb[3 * m], pb[3 * m + 1], pb[3 * m + 2], 0.f);
    __syncthreads();

    float best = 3.4e38f;
    int   bi   = 0;

    #pragma unroll 8
    for (int j = 0; j < CHM; j++) {
        const float4 p = sp[j];
        const float dx = p.x - qx, dy = p.y - qy, dz = p.z - qz;
        const float dc = fmaf(dx, dx, fmaf(dy, dy, dz * dz));
        if (dc < best) { best = dc; bi = j; }
    }
    g_nn_part[((size_t)b * NCHUNK + chunk) * NN + n] =
        packkey(best, chunk * CHM + bi);
}

// ---------------------------------------------------------------------------
// Kernel B: self-KNN, one warp per query, 1024-thread blocks, 64KB dynamic
// smem float4 tile. Distributed top-16 in lanes 0..15 (u64 keys).
// ---------------------------------------------------------------------------
__global__ __launch_bounds__(1024) void knn_kernel(const float* __restrict__ pcl)
{
    extern __shared__ float4 sp[];
    const int b = blockIdx.y;
    const int wrp  = threadIdx.x >> 5;
    const int lane = threadIdx.x & 31;
    const float* pb = pcl + (size_t)b * MM * 3;
    const unsigned FULL = 0xffffffffu;

    for (int m = threadIdx.x; m < MM; m += 1024)
        sp[m] = make_float4(pb[3 * m], pb[3 * m + 1], pb[3 * m + 2], 0.f);
    __syncthreads();

    const int m = blockIdx.x * 32 + wrp;
    const float4 q = sp[m];
    const float qx = q.x, qy = q.y, qz = q.z;

    unsigned long long key = 0xffffffffffffffffull;   // lanes 0..15 = list
    float kmd = 3.4e38f;                              // stale-safe threshold

    #pragma unroll 2
    for (int t = 0; t < MM / 32; t++) {
        const int j = lane + 32 * t;
        const float4 p = sp[j];
        const float dx = p.x - qx, dy = p.y - qy, dz = p.z - qz;
        const float dc = fmaf(dx, dx, fmaf(dy, dy, dz * dz));
        const unsigned long long kc_mine = packkey(dc, j);

        unsigned pend = __ballot_sync(FULL, dc <= kmd);
        if (pend) {
            bool inserted = false;
            do {
                const int src = __ffs(pend) - 1;
                pend &= pend - 1;
                const unsigned long long kc = __shfl_sync(FULL, kc_mine, src);
                const unsigned bal = __ballot_sync(FULL, key > kc) & 0xFFFFu;
                if (bal) {
                    const int p2 = __ffs(bal) - 1;
                    const unsigned long long up = __shfl_up_sync(FULL, key, 1);
                    if (lane == p2)      key = kc;
                    else if (lane > p2)  key = up;
                    inserted = true;
                }
            } while (pend);
            if (inserted) {
                const unsigned long long kmk = __shfl_sync(FULL, key, 15);
                kmd = __uint_as_float((unsigned)(kmk >> 32));
            }
        }
    }

    // rank 0 is the self point; emit ranks 1..15
    const int base = (b * MM + m) * KK;
    if (lane >= 1 && lane <= KK)
        g_knn[base + lane - 1] = (int)(key & 0xffffffffu);
}

// ---------------------------------------------------------------------------
// Kernel C: fused, BLOCK-COOPERATIVE GEMVs. 16 points per 128-thread block.
// Phase 1 (per-warp, 4 pts): NN-merge + gather + layer1 -> block-shared hb.
// Phases 2/4/5: output channels split across warps — lane owns output
// o = wrp*16 + (lane&15) and 8 points (ph = lane>>4). Weight loads are
// LDG.32 over 64B (1 line) and each matrix is read ONCE per 16 points
// (8.2KB/pt vs 33KB/pt before).
// ---------------------------------------------------------------------------
struct __align__(16) BlockSm {
    float ssum[16];
    float kd[16][16][4];   // [bp][k][dx,dy,dz,lw]
    float jw[16][16][2];   // [bp][k][jk(bits), lw]
    union {
        float hb[HH][16];              // 16 KB, phases 1-2
        struct {
            float df[3 * CC][16];      // 12 KB, phase 3-4
            float h1[CC][16];          //  4 KB, phase 4-5
        } s;
    } u;
};

__global__ __launch_bounds__(128, 5) void fused_kernel(
    const float* __restrict__ pcl,  const float* __restrict__ pcl_noise,
    const float* __restrict__ feature,
    const float* __restrict__ b2b,  const float* __restrict__ b1b,
    float* __restrict__ out)
{
    const int wrp  = threadIdx.x >> 5;
    const int lane = threadIdx.x & 31;
    const int gp0  = blockIdx.x * 16;        // block's first global point
    const int b    = gp0 >> 13;
    const int nb   = gp0 & (NN - 1);         // within-batch base index
    const int n0w  = nb + 4 * wrp;           // warp's first point
    const unsigned FULL = 0xffffffffu;

    __shared__ BlockSm S;

    // ======== Phase 1 (per-warp, 4 points): NN-merge, gather, layer 1 =======
    int ci[4];
    {
        const int p = lane >> 3, c = lane & 7;
        unsigned long long k =
            g_nn_part[((size_t)b * NCHUNK + c) * NN + (n0w + p)];
        unsigned long long o;
        o = __shfl_xor_sync(FULL, k, 4); if (o < k) k = o;
        o = __shfl_xor_sync(FULL, k, 2); if (o < k) k = o;
        o = __shfl_xor_sync(FULL, k, 1); if (o < k) k = o;
        #pragma unroll
        for (int p2 = 0; p2 < 4; p2++)
            ci[p2] = (int)(__shfl_sync(FULL, k, p2 * 8) & 0xffffffffu);
    }

    float qx[4], qy[4], qz[4], cpx[4], cpy[4], cpz[4];
    {
        const float4* q4 =
            (const float4*)(pcl_noise + ((size_t)b * NN + n0w) * 3);
        const float4 Q0 = q4[0], Q1 = q4[1], Q2 = q4[2];
        qx[0] = Q0.x; qy[0] = Q0.y; qz[0] = Q0.z;
        qx[1] = Q0.w; qy[1] = Q1.x; qz[1] = Q1.y;
        qx[2] = Q1.z; qy[2] = Q1.w; qz[2] = Q2.x;
        qx[3] = Q2.y; qy[3] = Q2.z; qz[3] = Q2.w;
        #pragma unroll
        for (int p = 0; p < 4; p++) {
            const float* cp = pcl + ((size_t)b * MM + ci[p]) * 3;
            cpx[p] = cp[0]; cpy[p] = cp[1]; cpz[p] = cp[2];
        }
    }

    #pragma unroll
    for (int p = 0; p < 4; p++) {
        const int bp = 4 * wrp + p;
        int jk = 0; float dx = 0.f, dy = 0.f, dz = 0.f, e = 0.f;
        if (lane < KK) {
            jk = g_knn[(b * MM + ci[p]) * KK + lane];
            const float* pp = pcl + ((size_t)b * MM + jk) * 3;
            dx = pp[0] - qx[p]; dy = pp[1] - qy[p]; dz = pp[2] - qz[p];
            e = expf(-10.0f * sqrtf(dx * dx + dy * dy + dz * dz));
        }
        float Sv = e;
        #pragma unroll
        for (int o = 16; o; o >>= 1) Sv += __shfl_xor_sync(FULL, Sv, o);
        const float lw = e / (Sv + 1e-7f);
        if (lane == 0) S.ssum[bp] = Sv / (Sv + 1e-7f);
        if (lane < KK) {
            *(float4*)&S.kd[bp][lane][0] = make_float4(dx, dy, dz, lw);
            *(float2*)&S.jw[bp][lane][0] =
                make_float2(__int_as_float(jk), lw);
        }
    }
    __syncwarp();

    // layer 1 (6 -> 256, BN folded): 2 passes of 4 channels x warp's 4 points
    #pragma unroll
    for (int s = 0; s < 2; s++) {
        float A0[4], A1[4], A2[4], t[4][4], h[4][4];
        #pragma unroll
        for (int i = 0; i < 4; i++) {
            const int c = lane + 32 * (4 * s + i);
            const float4 wA = *(const float4*)&g_l1A[c * 4];
            const float4 wT = *(const float4*)&g_l1T[c * 4];
            A0[i] = wA.x; A1[i] = wA.y; A2[i] = wA.z;
            #pragma unroll
            for (int p = 0; p < 4; p++) {
                t[i][p] = fmaf(wT.x, cpx[p], fmaf(wT.y, cpy[p],
                           fmaf(wT.z, cpz[p], wA.w)));
                h[i][p] = 0.f;
            }
        }
        for (int k = 0; k < KK; k++) {
            float4 kd[4];
            #pragma unroll
            for (int p = 0; p < 4; p++)
                kd[p] = *(const float4*)&S.kd[4 * wrp + p][k][0];
            #pragma unroll
            for (int i = 0; i < 4; i++) {
                #pragma unroll
                for (int p = 0; p < 4; p++) {
                    const float pre = fmaf(A0[i], kd[p].x, fmaf(A1[i], kd[p].y,
                                       fmaf(A2[i], kd[p].z, t[i][p])));
                    h[i][p] = fmaf(kd[p].w, fmaxf(pre, 0.f), h[i][p]);
                }
            }
        }
        #pragma unroll
        for (int i = 0; i < 4; i++) {
            const int c = lane + 32 * (4 * s + i);
            *(float4*)&S.u.hb[c][4 * wrp] =
                make_float4(h[i][0], h[i][1], h[i][2], h[i][3]);
        }
    }
    __syncthreads();

    // ======== Phase 2: layer 2 GEMV, outputs split across warps =============
    const int o = wrp * 16 + (lane & 15);   // this lane's output channel
    const int pbase = (lane >> 4) * 8;      // this lane's 8 points
    float pf[8];
    {
        unsigned long long acc[4] = {0, 0, 0, 0};
        const float* wcol = g_wt2b + o;
        #pragma unroll 4
        for (int c = 0; c < HH; c++) {
            const float wv = wcol[c * CC];
            const ulonglong2 hA = *(const ulonglong2*)&S.u.hb[c][pbase];
            const ulonglong2 hB = *(const ulonglong2*)&S.u.hb[c][pbase + 4];
            unsigned long long wd; DUP2(wd, wv);
            FMA2(acc[0], wd, hA.x); FMA2(acc[1], wd, hA.y);
            FMA2(acc[2], wd, hB.x); FMA2(acc[3], wd, hB.y);
        }
        #pragma unroll
        for (int g = 0; g < 4; g++)
            UNPK2(pf[2 * g], pf[2 * g + 1], acc[g]);
        const float bb = b2b[o];
        #pragma unroll
        for (int i = 0; i < 8; i++)
            pf[i] = fmaf(bb, S.ssum[pbase + i], pf[i]);
    }
    __syncthreads();   // all reads of hb complete before df overwrites it

    // ======== Phase 3: close/co features (per-warp) + stage df ==============
    {
        const int o1 = 2 * lane;
        float cf0[4], cf1[4], co0[4], co1[4];
        #pragma unroll
        for (int p = 0; p < 4; p++) {
            const float2 f =
                *(const float2*)(feature + ((size_t)b * MM + ci[p]) * CC + o1);
            cf0[p] = f.x; cf1[p] = f.y; co0[p] = 0.f; co1[p] = 0.f;
        }
        for (int k = 0; k < KK; k++) {
            #pragma unroll
            for (int p = 0; p < 4; p++) {
                const float2 jw = *(const float2*)&S.jw[4 * wrp + p][k][0];
                const int j = __float_as_int(jw.x);
                const float2 f =
                    *(const float2*)(feature + ((size_t)b * MM + j) * CC + o1);
                co0[p] = fmaf(jw.y, f.x, co0[p]);
                co1[p] = fmaf(jw.y, f.y, co1[p]);
            }
        }
        *(float4*)&S.u.s.df[o1][4 * wrp] =
            make_float4(cf0[0], cf0[1], cf0[2], cf0[3]);
        *(float4*)&S.u.s.df[o1 + 1][4 * wrp] =
            make_float4(cf1[0], cf1[1], cf1[2], cf1[3]);
        *(float4*)&S.u.s.df[CC + o1][4 * wrp] =
            make_float4(co0[0], co0[1], co0[2], co0[3]);
        *(float4*)&S.u.s.df[CC + o1 + 1][4 * wrp] =
            make_float4(co1[0], co1[1], co1[2], co1[3]);
        // point_feature rows (distributed by o, 8 points per lane)
        *(float4*)&S.u.s.df[2 * CC + o][pbase] =
            make_float4(pf[0], pf[1], pf[2], pf[3]);
        *(float4*)&S.u.s.df[2 * CC + o][pbase + 4] =
            make_float4(pf[4], pf[5], pf[6], pf[7]);
    }
    __syncthreads();

    // ======== Phase 4: final MLP layer 1 (192 -> 64), BN + ReLU =============
    {
        unsigned long long acc[4] = {0, 0, 0, 0};
        const float* wcol = g_wt1a + o;
        #pragma unroll 4
        for (int c = 0; c < 3 * CC; c++) {
            const float wv = wcol[c * CC];
            const ulonglong2 dA = *(const ulonglong2*)&S.u.s.df[c][pbase];
            const ulonglong2 dB = *(const ulonglong2*)&S.u.s.df[c][pbase + 4];
            unsigned long long wd; DUP2(wd, wv);
            FMA2(acc[0], wd, dA.x); FMA2(acc[1], wd, dA.y);
            FMA2(acc[2], wd, dB.x); FMA2(acc[3], wd, dB.y);
        }
        float ax[8];
        #pragma unroll
        for (int g = 0; g < 4; g++)
            UNPK2(ax[2 * g], ax[2 * g + 1], acc[g]);
        const float s1 = g_f1s[o], b1 = g_f1b[o];
        float hx[8];
        #pragma unroll
        for (int i = 0; i < 8; i++)
            hx[i] = fmaxf(fmaf(ax[i], s1, b1), 0.f);
        *(float4*)&S.u.s.h1[o][pbase] =
            make_float4(hx[0], hx[1], hx[2], hx[3]);
        *(float4*)&S.u.s.h1[o][pbase + 4] =
            make_float4(hx[4], hx[5], hx[6], hx[7]);
    }
    __syncthreads();

    // ======== Phase 5: final MLP layer 2 (64 -> 64) + store =================
    {
        unsigned long long acc[4] = {0, 0, 0, 0};
        const float* wcol = g_wt1b + o;
        #pragma unroll 4
        for (int c = 0; c < CC; c++) {
            const float wv = wcol[c * CC];
            const ulonglong2 hA = *(const ulonglong2*)&S.u.s.h1[c][pbase];
            const ulonglong2 hB = *(const ulonglong2*)&S.u.s.h1[c][pbase + 4];
            unsigned long long wd; DUP2(wd, wv);
            FMA2(acc[0], wd, hA.x); FMA2(acc[1], wd, hA.y);
            FMA2(acc[2], wd, hB.x); FMA2(acc[3], wd, hB.y);
        }
        float rx[8];
        #pragma unroll
        for (int g = 0; g < 4; g++)
            UNPK2(rx[2 * g], rx[2 * g + 1], acc[g]);
        const float bo = b1b[o];
        #pragma unroll
        for (int i = 0; i < 8; i++)
            out[((size_t)b * NN + nb + pbase + i) * CC + o] = rx[i] + bo;
    }
}

// ---------------------------------------------------------------------------
extern "C" void kernel_launch(void* const* d_in, const int* in_sizes, int n_in,
                              void* d_out, int out_size)
{
    (void)in_sizes; (void)n_in; (void)out_size;
    const float* pcl       = (const float*)d_in[0];
    const float* pcl_noise = (const float*)d_in[1];
    const float* feature   = (const float*)d_in[2];
    const float* w2a  = (const float*)d_in[3];
    const float* b2a  = (const float*)d_in[4];
    const float* g2a  = (const float*)d_in[5];
    const float* bt2a = (const float*)d_in[6];
    const float* w2b  = (const float*)d_in[7];
    const float* b2b  = (const float*)d_in[8];
    const float* w1a  = (const float*)d_in[9];
    const float* b1a  = (const float*)d_in[10];
    const float* g1a  = (const float*)d_in[11];
    const float* bt1a = (const float*)d_in[12];
    const float* w1b  = (const float*)d_in[13];
    const float* b1b  = (const float*)d_in[14];
    float* out = (float*)d_out;

    static int knn_smem_set = 0;
    if (!knn_smem_set) {
        cudaFuncSetAttribute(knn_kernel,
            cudaFuncAttributeMaxDynamicSharedMemorySize, MM * 16);
        knn_smem_set = 1;
    }

    prep_kernel<<<64, 256>>>(w2a, b2a, g2a, bt2a, w2b, w1a, b1a, g1a, bt1a, w1b);
    nn_part_kernel<<<dim3(NN / 128, NCHUNK, BB), 128>>>(pcl, pcl_noise);
    knn_kernel<<<dim3(MM / 32, BB), 1024, MM * 16>>>(pcl);
    fused_kernel<<<(BB * NN) / 16, 128>>>(
        pcl, pcl_noise, feature, b2b, b1b, out);
}

// round 14
// speedup vs baseline: 1.2786x; 1.2786x over previous
#include <cuda_runtime.h>
#include <math.h>

#define BB  2
#define NN  8192
#define MM  4096
#define CC  64
#define KK  15      // K-1 neighbors actually used
#define HH  256
#define NCHUNK 8
#define CHM (MM / NCHUNK)   // 512

// Scratch (allocation-free rule: __device__ globals)
__device__ unsigned long long g_nn_part[BB * NCHUNK * NN];
__device__ int   g_knn[BB * MM * KK];
// prepped weights
__device__ float g_l1A[HH * 4];          // [c][{A0,A1,A2,B}]  (BN-folded)
__device__ float g_l1T[HH * 4];          // [c][{A3,A4,A5,0}]  (BN-folded)
__device__ float g_wt2b[HH * CC];        // [c][o]
__device__ float g_wt1a[3 * CC * CC];    // [c][o]
__device__ float g_wt1b[CC * CC];        // [c][o]
__device__ float g_f1s[CC];              // g1a*invs
__device__ float g_f1b[CC];              // b1a*g' + bt1a

#define FMA2(acc, a, b) \
    asm("fma.rn.f32x2 %0, %1, %2, %0;" : "+l"(acc) : "l"(a), "l"(b))
#define ADD2(acc, a) \
    asm("add.rn.f32x2 %0, %0, %1;" : "+l"(acc) : "l"(a))
#define UNPK2(lo, hi, v) \
    asm("mov.b64 {%0, %1}, %2;" : "=f"(lo), "=f"(hi) : "l"(v))
#define DUP2(out, v) \
    asm("mov.b64 %0, {%1, %1};" : "=l"(out) : "f"(v))

static __device__ __forceinline__ unsigned long long packkey(float d, int idx) {
    return ((unsigned long long)__float_as_uint(d) << 32) | (unsigned)idx;
}

// ---------------------------------------------------------------------------
// Kernel P: fold BN + transpose weight prep.
// ---------------------------------------------------------------------------
__global__ __launch_bounds__(256) void prep_kernel(
    const float* __restrict__ w2a, const float* __restrict__ b2a,
    const float* __restrict__ g2a, const float* __restrict__ bt2a,
    const float* __restrict__ w2b,
    const float* __restrict__ w1a, const float* __restrict__ b1a,
    const float* __restrict__ g1a, const float* __restrict__ bt1a,
    const float* __restrict__ w1b)
{
    const float invs = rsqrtf(1.0f + 1e-5f);
    const int t = blockIdx.x * 256 + threadIdx.x;
    const int stride = gridDim.x * 256;

    for (int c = t; c < HH; c += stride) {
        const float gp = g2a[c] * invs;
        g_l1A[c * 4 + 0] = w2a[c * 6 + 0] * gp;
        g_l1A[c * 4 + 1] = w2a[c * 6 + 1] * gp;
        g_l1A[c * 4 + 2] = w2a[c * 6 + 2] * gp;
        g_l1A[c * 4 + 3] = b2a[c] * gp + bt2a[c];
        g_l1T[c * 4 + 0] = w2a[c * 6 + 3] * gp;
        g_l1T[c * 4 + 1] = w2a[c * 6 + 4] * gp;
        g_l1T[c * 4 + 2] = w2a[c * 6 + 5] * gp;
        g_l1T[c * 4 + 3] = 0.f;
    }
    for (int idx = t; idx < HH * CC; idx += stride) {
        int c = idx / CC, o = idx - c * CC;
        g_wt2b[idx] = w2b[o * HH + c];
    }
    for (int idx = t; idx < 3 * CC * CC; idx += stride) {
        int c = idx / CC, o = idx - c * CC;
        g_wt1a[idx] = w1a[o * (3 * CC) + c];
    }
    for (int idx = t; idx < CC * CC; idx += stride) {
        int c = idx / CC, o = idx - c * CC;
        g_wt1b[idx] = w1b[o * CC + c];
    }
    for (int o = t; o < CC; o += stride) {
        const float s = g1a[o] * invs;
        g_f1s[o] = s;
        g_f1b[o] = b1a[o] * s + bt1a[o];
    }
}

// ---------------------------------------------------------------------------
// Kernel A: partial argmin over a 512-candidate chunk. float4 smem tile;
// exact difference-based distance (matches reference conditioning).
// ---------------------------------------------------------------------------
__global__ __launch_bounds__(128) void nn_part_kernel(
    const float* __restrict__ pcl, const float* __restrict__ pcl_noise)
{
    const int b = blockIdx.z;
    const int chunk = blockIdx.y;
    const int n = blockIdx.x * 128 + threadIdx.x;
    const float* pb = pcl + (size_t)b * MM * 3 + (size_t)chunk * CHM * 3;

    const float qx = pcl_noise[((size_t)b * NN + n) * 3 + 0];
    const float qy = pcl_noise[((size_t)b * NN + n) * 3 + 1];
    const float qz = pcl_noise[((size_t)b * NN + n) * 3 + 2];

    __shared__ float4 sp[CHM];
    for (int m = threadIdx.x; m < CHM; m += 128)
        sp[m] = make_float4(pb[3 * m], pb[3 * m + 1], pb[3 * m + 2], 0.f);
    __syncthreads();

    float best = 3.4e38f;
    int   bi   = 0;

    #pragma unroll 8
    for (int j = 0; j < CHM; j++) {
        const float4 p = sp[j];
        const float dx = p.x - qx, dy = p.y - qy, dz = p.z - qz;
        const float dc = fmaf(dx, dx, fmaf(dy, dy, dz * dz));
        if (dc < best) { best = dc; bi = j; }
    }
    g_nn_part[((size_t)b * NCHUNK + chunk) * NN + n] =
        packkey(best, chunk * CHM + bi);
}

// ---------------------------------------------------------------------------
// Kernel B: self-KNN, one warp per query, 1024-thread blocks, 64KB dynamic
// smem float4 tile. Distributed top-16 in lanes 0..15 (u64 keys).
// ---------------------------------------------------------------------------
__global__ __launch_bounds__(1024) void knn_kernel(const float* __restrict__ pcl)
{
    extern __shared__ float4 sp[];
    const int b = blockIdx.y;
    const int wrp  = threadIdx.x >> 5;
    const int lane = threadIdx.x & 31;
    const float* pb = pcl + (size_t)b * MM * 3;
    const unsigned FULL = 0xffffffffu;

    for (int m = threadIdx.x; m < MM; m += 1024)
        sp[m] = make_float4(pb[3 * m], pb[3 * m + 1], pb[3 * m + 2], 0.f);
    __syncthreads();

    const int m = blockIdx.x * 32 + wrp;
    const float4 q = sp[m];
    const float qx = q.x, qy = q.y, qz = q.z;

    unsigned long long key = 0xffffffffffffffffull;   // lanes 0..15 = list
    float kmd = 3.4e38f;                              // stale-safe threshold

    #pragma unroll 2
    for (int t = 0; t < MM / 32; t++) {
        const int j = lane + 32 * t;
        const float4 p = sp[j];
        const float dx = p.x - qx, dy = p.y - qy, dz = p.z - qz;
        const float dc = fmaf(dx, dx, fmaf(dy, dy, dz * dz));
        const unsigned long long kc_mine = packkey(dc, j);

        unsigned pend = __ballot_sync(FULL, dc <= kmd);
        if (pend) {
            bool inserted = false;
            do {
                const int src = __ffs(pend) - 1;
                pend &= pend - 1;
                const unsigned long long kc = __shfl_sync(FULL, kc_mine, src);
                const unsigned bal = __ballot_sync(FULL, key > kc) & 0xFFFFu;
                if (bal) {
                    const int p2 = __ffs(bal) - 1;
                    const unsigned long long up = __shfl_up_sync(FULL, key, 1);
                    if (lane == p2)      key = kc;
                    else if (lane > p2)  key = up;
                    inserted = true;
                }
            } while (pend);
            if (inserted) {
                const unsigned long long kmk = __shfl_sync(FULL, key, 15);
                kmd = __uint_as_float((unsigned)(kmk >> 32));
            }
        }
    }

    // rank 0 is the self point; emit ranks 1..15
    const int base = (b * MM + m) * KK;
    if (lane >= 1 && lane <= KK)
        g_knn[base + lane - 1] = (int)(key & 0xffffffffu);
}

// ---------------------------------------------------------------------------
// Kernel C: fused NN-merge + gather + MLPs. One warp per 4 points (best
// measured config: 96 regs, occ ~29%). Layer 1 in 2 channel-half passes.
// ---------------------------------------------------------------------------
struct __align__(16) WarpSm {
    float kd[4][16][4];   // [p][k][dx,dy,dz,lw]
    float jw[4][16][2];   // [p][k][jk(bits), lw]
    union {
        float hb[HH][4];              // 4096 B, phase 1-2
        struct {
            float df[3 * CC][4];      // 3072 B, phase 3
            float h1[CC][4];          // 1024 B, phase 4
        } s;
    } u;
};

__global__ __launch_bounds__(128, 5) void fused_kernel(
    const float* __restrict__ pcl,  const float* __restrict__ pcl_noise,
    const float* __restrict__ feature,
    const float* __restrict__ b2b,  const float* __restrict__ b1b,
    float* __restrict__ out)
{
    const int wrp  = threadIdx.x >> 5;
    const int lane = threadIdx.x & 31;
    const int pt0  = (blockIdx.x * 4 + wrp) * 4;   // 4 consecutive points
    const int b    = pt0 >> 13;
    const int n0   = pt0 & (NN - 1);
    const unsigned FULL = 0xffffffffu;

    __shared__ WarpSm sm[4];
    WarpSm& S = sm[wrp];

    // ---- distributed NN-merge: lane = p*8 + chunk --------------------------
    int ci[4];
    {
        const int p = lane >> 3, c = lane & 7;
        unsigned long long k =
            g_nn_part[((size_t)b * NCHUNK + c) * NN + (n0 + p)];
        unsigned long long o;
        o = __shfl_xor_sync(FULL, k, 4); if (o < k) k = o;
        o = __shfl_xor_sync(FULL, k, 2); if (o < k) k = o;
        o = __shfl_xor_sync(FULL, k, 1); if (o < k) k = o;
        #pragma unroll
        for (int p2 = 0; p2 < 4; p2++)
            ci[p2] = (int)(__shfl_sync(FULL, k, p2 * 8) & 0xffffffffu);
    }

    // ---- query coords (3x LDG.128 broadcast) + close points ----------------
    float qx[4], qy[4], qz[4], cpx[4], cpy[4], cpz[4];
    {
        const float4* q4 =
            (const float4*)(pcl_noise + ((size_t)b * NN + n0) * 3);
        const float4 Q0 = q4[0], Q1 = q4[1], Q2 = q4[2];
        qx[0] = Q0.x; qy[0] = Q0.y; qz[0] = Q0.z;
        qx[1] = Q0.w; qy[1] = Q1.x; qz[1] = Q1.y;
        qx[2] = Q1.z; qy[2] = Q1.w; qz[2] = Q2.x;
        qx[3] = Q2.y; qy[3] = Q2.z; qz[3] = Q2.w;
        #pragma unroll
        for (int p = 0; p < 4; p++) {
            const float* cp = pcl + ((size_t)b * MM + ci[p]) * 3;
            cpx[p] = cp[0]; cpy[p] = cp[1]; cpz[p] = cp[2];
        }
    }

    // ---- neighbors: lane k owns neighbor k of each point -------------------
    float ssum[4];
    #pragma unroll
    for (int p = 0; p < 4; p++) {
        int jk = 0; float dx = 0.f, dy = 0.f, dz = 0.f, e = 0.f;
        if (lane < KK) {
            jk = g_knn[(b * MM + ci[p]) * KK + lane];
            const float* pp = pcl + ((size_t)b * MM + jk) * 3;
            dx = pp[0] - qx[p]; dy = pp[1] - qy[p]; dz = pp[2] - qz[p];
            e = expf(-10.0f * sqrtf(dx * dx + dy * dy + dz * dz));
        }
        float Sv = e;
        #pragma unroll
        for (int o = 16; o; o >>= 1) Sv += __shfl_xor_sync(FULL, Sv, o);
        const float lw = e / (Sv + 1e-7f);
        ssum[p] = Sv / (Sv + 1e-7f);
        if (lane < KK) {
            *(float4*)&S.kd[p][lane][0] = make_float4(dx, dy, dz, lw);
            *(float2*)&S.jw[p][lane][0] =
                make_float2(__int_as_float(jk), lw);
        }
    }
    __syncwarp();

    // ---- layer 1 (6 -> 256, BN folded): 2 passes of 4 channels x 4 points --
    #pragma unroll
    for (int s = 0; s < 2; s++) {
        float A0[4], A1[4], A2[4], t[4][4], h[4][4];
        #pragma unroll
        for (int i = 0; i < 4; i++) {
            const int c = lane + 32 * (4 * s + i);
            const float4 wA = *(const float4*)&g_l1A[c * 4];
            const float4 wT = *(const float4*)&g_l1T[c * 4];
            A0[i] = wA.x; A1[i] = wA.y; A2[i] = wA.z;
            #pragma unroll
            for (int p = 0; p < 4; p++) {
                t[i][p] = fmaf(wT.x, cpx[p], fmaf(wT.y, cpy[p],
                           fmaf(wT.z, cpz[p], wA.w)));
                h[i][p] = 0.f;
            }
        }
        for (int k = 0; k < KK; k++) {
            float4 kd[4];
            #pragma unroll
            for (int p = 0; p < 4; p++) kd[p] = *(const float4*)&S.kd[p][k][0];
            #pragma unroll
            for (int i = 0; i < 4; i++) {
                #pragma unroll
                for (int p = 0; p < 4; p++) {
                    const float pre = fmaf(A0[i], kd[p].x, fmaf(A1[i], kd[p].y,
                                       fmaf(A2[i], kd[p].z, t[i][p])));
                    h[i][p] = fmaf(kd[p].w, fmaxf(pre, 0.f), h[i][p]);
                }
            }
        }
        #pragma unroll
        for (int i = 0; i < 4; i++) {
            const int c = lane + 32 * (4 * s + i);
            *(float4*)&S.u.hb[c][0] =
                make_float4(h[i][0], h[i][1], h[i][2], h[i][3]);
        }
    }
    __syncwarp();

    const int o1 = 2 * lane;

    // ---- layer 2: 256 -> 64, FFMA2, split even/odd chains ------------------
    unsigned long long aXe0 = 0, aXe1 = 0, aXo0 = 0, aXo1 = 0;
    unsigned long long aYe0 = 0, aYe1 = 0, aYo0 = 0, aYo1 = 0;
    {
        const float* wrow = g_wt2b + o1;
        #pragma unroll 4
        for (int c = 0; c < HH; c += 2) {
            const ulonglong2 hE = *(const ulonglong2*)&S.u.hb[c][0];
            const ulonglong2 hO = *(const ulonglong2*)&S.u.hb[c + 1][0];
            const float2 wE = *(const float2*)(wrow + c * CC);
            const float2 wO = *(const float2*)(wrow + (c + 1) * CC);
            unsigned long long w;
            DUP2(w, wE.x); FMA2(aXe0, w, hE.x); FMA2(aXe1, w, hE.y);
            DUP2(w, wE.y); FMA2(aYe0, w, hE.x); FMA2(aYe1, w, hE.y);
            DUP2(w, wO.x); FMA2(aXo0, w, hO.x); FMA2(aXo1, w, hO.y);
            DUP2(w, wO.y); FMA2(aYo0, w, hO.x); FMA2(aYo1, w, hO.y);
        }
    }
    ADD2(aXe0, aXo0); ADD2(aXe1, aXo1);
    ADD2(aYe0, aYo0); ADD2(aYe1, aYo1);
    float pfx[4], pfy[4];
    UNPK2(pfx[0], pfx[1], aXe0); UNPK2(pfx[2], pfx[3], aXe1);
    UNPK2(pfy[0], pfy[1], aYe0); UNPK2(pfy[2], pfy[3], aYe1);
    {
        const float2 bb2 = *(const float2*)(b2b + o1);
        #pragma unroll
        for (int p = 0; p < 4; p++) {
            pfx[p] = fmaf(bb2.x, ssum[p], pfx[p]);
            pfy[p] = fmaf(bb2.y, ssum[p], pfy[p]);
        }
    }

    // ---- close_feat + co_feature -------------------------------------------
    float cf0[4], cf1[4], co0[4], co1[4];
    #pragma unroll
    for (int p = 0; p < 4; p++) {
        const float2 f =
            *(const float2*)(feature + ((size_t)b * MM + ci[p]) * CC + o1);
        cf0[p] = f.x; cf1[p] = f.y; co0[p] = 0.f; co1[p] = 0.f;
    }
    for (int k = 0; k < KK; k++) {
        #pragma unroll
        for (int p = 0; p < 4; p++) {
            const float2 jw = *(const float2*)&S.jw[p][k][0];
            const int j = __float_as_int(jw.x);
            const float2 f =
                *(const float2*)(feature + ((size_t)b * MM + j) * CC + o1);
            co0[p] = fmaf(jw.y, f.x, co0[p]);
            co1[p] = fmaf(jw.y, f.y, co1[p]);
        }
    }
    __syncwarp();   // all lanes done reading hb before df overwrites it

    *(float4*)&S.u.s.df[o1][0]          = make_float4(cf0[0], cf0[1], cf0[2], cf0[3]);
    *(float4*)&S.u.s.df[o1 + 1][0]      = make_float4(cf1[0], cf1[1], cf1[2], cf1[3]);
    *(float4*)&S.u.s.df[CC + o1][0]     = make_float4(co0[0], co0[1], co0[2], co0[3]);
    *(float4*)&S.u.s.df[CC + o1 + 1][0] = make_float4(co1[0], co1[1], co1[2], co1[3]);
    *(float4*)&S.u.s.df[2 * CC + o1][0]     = make_float4(pfx[0], pfx[1], pfx[2], pfx[3]);
    *(float4*)&S.u.s.df[2 * CC + o1 + 1][0] = make_float4(pfy[0], pfy[1], pfy[2], pfy[3]);
    __syncwarp();

    // ---- final MLP layer 1: 192 -> 64, BN folded + ReLU --------------------
    unsigned long long fXe0 = 0, fXe1 = 0, fXo0 = 0, fXo1 = 0;
    unsigned long long fYe0 = 0, fYe1 = 0, fYo0 = 0, fYo1 = 0;
    {
        const float* wrow = g_wt1a + o1;
        #pragma unroll 4
        for (int c = 0; c < 3 * CC; c += 2) {
            const ulonglong2 dE = *(const ulonglong2*)&S.u.s.df[c][0];
            const ulonglong2 dO = *(const ulonglong2*)&S.u.s.df[c + 1][0];
            const float2 wE = *(const float2*)(wrow + c * CC);
            const float2 wO = *(const float2*)(wrow + (c + 1) * CC);
            unsigned long long w;
            DUP2(w, wE.x); FMA2(fXe0, w, dE.x); FMA2(fXe1, w, dE.y);
            DUP2(w, wE.y); FMA2(fYe0, w, dE.x); FMA2(fYe1, w, dE.y);
            DUP2(w, wO.x); FMA2(fXo0, w, dO.x); FMA2(fXo1, w, dO.y);
            DUP2(w, wO.y); FMA2(fYo0, w, dO.x); FMA2(fYo1, w, dO.y);
        }
    }
    ADD2(fXe0, fXo0); ADD2(fXe1, fXo1);
    ADD2(fYe0, fYo0); ADD2(fYe1, fYo1);
    {
        float ax[4], ay[4];
        UNPK2(ax[0], ax[1], fXe0); UNPK2(ax[2], ax[3], fXe1);
        UNPK2(ay[0], ay[1], fYe0); UNPK2(ay[2], ay[3], fYe1);
        const float2 s2 = *(const float2*)(g_f1s + o1);
        const float2 b2 = *(const float2*)(g_f1b + o1);
        float hx[4], hy[4];
        #pragma unroll
        for (int p = 0; p < 4; p++) {
            hx[p] = fmaxf(fmaf(ax[p], s2.x, b2.x), 0.f);
            hy[p] = fmaxf(fmaf(ay[p], s2.y, b2.y), 0.f);
        }
        *(float4*)&S.u.s.h1[o1][0]     = make_float4(hx[0], hx[1], hx[2], hx[3]);
        *(float4*)&S.u.s.h1[o1 + 1][0] = make_float4(hy[0], hy[1], hy[2], hy[3]);
    }
    __syncwarp();

    // ---- final MLP layer 2: 64 -> 64 ---------------------------------------
    unsigned long long rXe0 = 0, rXe1 = 0, rXo0 = 0, rXo1 = 0;
    unsigned long long rYe0 = 0, rYe1 = 0, rYo0 = 0, rYo1 = 0;
    {
        const float* wrow = g_wt1b + o1;
        #pragma unroll 4
        for (int c = 0; c < CC; c += 2) {
            const ulonglong2 hE = *(const ulonglong2*)&S.u.s.h1[c][0];
            const ulonglong2 hO = *(const ulonglong2*)&S.u.s.h1[c + 1][0];
            const float2 wE = *(const float2*)(wrow + c * CC);
            const float2 wO = *(const float2*)(wrow + (c + 1) * CC);
            unsigned long long w;
            DUP2(w, wE.x); FMA2(rXe0, w, hE.x); FMA2(rXe1, w, hE.y);
            DUP2(w, wE.y); FMA2(rYe0, w, hE.x); FMA2(rYe1, w, hE.y);
            DUP2(w, wO.x); FMA2(rXo0, w, hO.x); FMA2(rXo1, w, hO.y);
            DUP2(w, wO.y); FMA2(rYo0, w, hO.x); FMA2(rYo1, w, hO.y);
        }
    }
    ADD2(rXe0, rXo0); ADD2(rXe1, rXo1);
    ADD2(rYe0, rYo0); ADD2(rYe1, rYo1);
    {
        float rx[4], ry[4];
        UNPK2(rx[0], rx[1], rXe0); UNPK2(rx[2], rx[3], rXe1);
        UNPK2(ry[0], ry[1], rYe0); UNPK2(ry[2], ry[3], rYe1);
        const float2 bo = *(const float2*)(b1b + o1);
        #pragma unroll
        for (int p = 0; p < 4; p++) {
            *(float2*)(out + ((size_t)b * NN + n0 + p) * CC + o1) =
                make_float2(rx[p] + bo.x, ry[p] + bo.y);
        }
    }
}

// ---------------------------------------------------------------------------
extern "C" void kernel_launch(void* const* d_in, const int* in_sizes, int n_in,
                              void* d_out, int out_size)
{
    (void)in_sizes; (void)n_in; (void)out_size;
    const float* pcl       = (const float*)d_in[0];
    const float* pcl_noise = (const float*)d_in[1];
    const float* feature   = (const float*)d_in[2];
    const float* w2a  = (const float*)d_in[3];
    const float* b2a  = (const float*)d_in[4];
    const float* g2a  = (const float*)d_in[5];
    const float* bt2a = (const float*)d_in[6];
    const float* w2b  = (const float*)d_in[7];
    const float* b2b  = (const float*)d_in[8];
    const float* w1a  = (const float*)d_in[9];
    const float* b1a  = (const float*)d_in[10];
    const float* g1a  = (const float*)d_in[11];
    const float* bt1a = (const float*)d_in[12];
    const float* w1b  = (const float*)d_in[13];
    const float* b1b  = (const float*)d_in[14];
    float* out = (float*)d_out;

    static cudaStream_t s1 = nullptr;
    static cudaEvent_t  evF = nullptr, evJ = nullptr;
    if (!s1) {
        cudaStreamCreateWithFlags(&s1, cudaStreamNonBlocking);
        cudaEventCreateWithFlags(&evF, cudaEventDisableTiming);
        cudaEventCreateWithFlags(&evJ, cudaEventDisableTiming);
        cudaFuncSetAttribute(knn_kernel,
            cudaFuncAttributeMaxDynamicSharedMemorySize, MM * 16);
    }

    // Fork: prep + nn_part run on side stream, overlapped with knn (main).
    cudaEventRecord(evF, 0);
    cudaStreamWaitEvent(s1, evF, 0);
    prep_kernel<<<64, 256, 0, s1>>>(w2a, b2a, g2a, bt2a, w2b,
                                    w1a, b1a, g1a, bt1a, w1b);
    nn_part_kernel<<<dim3(NN / 128, NCHUNK, BB), 128, 0, s1>>>(pcl, pcl_noise);
    cudaEventRecord(evJ, s1);

    knn_kernel<<<dim3(MM / 32, BB), 1024, MM * 16>>>(pcl);

    // Join: fused needs prep + nn_part + knn.
    cudaStreamWaitEvent((cudaStream_t)0, evJ, 0);
    fused_kernel<<<(BB * NN) / 16, 128>>>(
        pcl, pcl_noise, feature, b2b, b1b, out);
}